// round 5
// baseline (speedup 1.0000x reference)
#include <cuda_runtime.h>
#include <cuda_bf16.h>

// Problem constants
#define BATCH     8192
#define NUM_CODES 16
#define BOOK_SIZE 1024
#define EMBED_DIM 64

// Tiling
#define MB    128   // x rows per CTA
#define CHUNK 64    // codebook rows per smem tile

#define NPAIR (BATCH * NUM_CODES)
#define CW_ELEMS ((size_t)BATCH * NUM_CODES * EMBED_DIM)   // 8,388,608

// Near-tie band on EXACT distance gap (ulp(128) = 1.53e-5; reference noise <~3 ulp)
#define TIE_EPS 4e-5

// Scratch (device globals; no allocation allowed)
__device__ float g_c2 [NUM_CODES * BOOK_SIZE];
__device__ int   g_i1 [NPAIR];
__device__ int   g_i2 [NPAIR];
__device__ float g_v1 [NPAIR];
__device__ float g_v2 [NPAIR];
__device__ int   g_idx[NPAIR];

// ---------------------------------------------------------------------------
// f32x2 packed helpers (2 fp32 MACs per instruction on the fma pipe)
// ---------------------------------------------------------------------------
__device__ __forceinline__ void fma2(unsigned long long& acc,
                                     unsigned long long a,
                                     unsigned long long b) {
    asm("fma.rn.f32x2 %0, %1, %2, %0;" : "+l"(acc) : "l"(a), "l"(b));
}
__device__ __forceinline__ unsigned long long dup2(float v) {
    unsigned long long r;
    asm("mov.b64 %0, {%1, %1};" : "=l"(r) : "f"(v));
    return r;
}
__device__ __forceinline__ void unpack2(unsigned long long v, float& lo, float& hi) {
    asm("mov.b64 {%0, %1}, %2;" : "=f"(lo), "=f"(hi) : "l"(v));
}

// ---------------------------------------------------------------------------
// Kernel 0: codebook squared norms (fast path ranking only; refine re-derives
// exact values for borderline pairs, so the order here is uncritical).
// ---------------------------------------------------------------------------
__global__ void c2_kernel(const float* __restrict__ cb) {
    int code = blockIdx.x * blockDim.x + threadIdx.x;
    if (code < NUM_CODES * BOOK_SIZE) {
        const float4* p = (const float4*)(cb + (size_t)code * EMBED_DIM);
        float s = 0.f;
        #pragma unroll
        for (int i = 0; i < EMBED_DIM / 4; i++) {
            float4 v = p[i];
            s += v.x * v.x + v.y * v.y + v.z * v.z + v.w * v.w;
        }
        g_c2[code] = s;
    }
}

// ---------------------------------------------------------------------------
// Kernel 1: top-2 argmin over (c2 - 2*dot)  [x2 is row-constant -> dropped].
// Grid (BATCH/MB, NUM_CODES), 256 threads.
//   tx = tid & 15  -> code lane (codes c0 + tx + 16*j, j=0..3)
//   ty = tid >> 4  -> row group (rows ty*8 .. ty*8+7, paired for f32x2)
// ---------------------------------------------------------------------------
__global__ void __launch_bounds__(256)
argmin_kernel(const float* __restrict__ x, const float* __restrict__ cb) {
    __shared__ float xs[EMBED_DIM][MB];      // 32 KB, transposed
    __shared__ float cs[EMBED_DIM][CHUNK];   // 16 KB, transposed

    const int tid  = threadIdx.x;
    const int tx   = tid & 15;
    const int ty   = tid >> 4;
    const int n    = blockIdx.y;
    const int row0 = blockIdx.x * MB;

    const float* xbase = x  + (size_t)row0 * (NUM_CODES * EMBED_DIM) + n * EMBED_DIM;
    const float* cbase = cb + (size_t)n * (BOOK_SIZE * EMBED_DIM);

    // Load x tile (transposed). 128 rows x 16 float4 columns.
    for (int it = tid; it < MB * (EMBED_DIM / 4); it += 256) {
        int r  = it >> 4;
        int c4 = it & 15;
        float4 v = *(const float4*)(xbase + (size_t)r * (NUM_CODES * EMBED_DIM) + c4 * 4);
        xs[c4 * 4 + 0][r] = v.x;
        xs[c4 * 4 + 1][r] = v.y;
        xs[c4 * 4 + 2][r] = v.z;
        xs[c4 * 4 + 3][r] = v.w;
    }

    float v1[8], v2[8];
    int   i1[8], i2[8];
    #pragma unroll
    for (int i = 0; i < 8; i++) {
        v1[i] = 3.4e38f; v2[i] = 3.4e38f; i1[i] = 0; i2[i] = 0;
    }

    unsigned long long acc2[4][4];
    #pragma unroll
    for (int p = 0; p < 4; p++)
        #pragma unroll
        for (int j = 0; j < 4; j++) acc2[p][j] = 0ull;

    for (int c0 = 0; c0 < BOOK_SIZE; c0 += CHUNK) {
        __syncthreads();
        // Load code tile (transposed)
        for (int it = tid; it < CHUNK * (EMBED_DIM / 4); it += 256) {
            int r  = it >> 4;
            int c4 = it & 15;
            float4 v = *(const float4*)(cbase + (size_t)(c0 + r) * EMBED_DIM + c4 * 4);
            cs[c4 * 4 + 0][r] = v.x;
            cs[c4 * 4 + 1][r] = v.y;
            cs[c4 * 4 + 2][r] = v.z;
            cs[c4 * 4 + 3][r] = v.w;
        }
        __syncthreads();

        float c2v[4];
        #pragma unroll
        for (int j = 0; j < 4; j++)
            c2v[j] = __ldg(&g_c2[n * BOOK_SIZE + c0 + tx + 16 * j]);

        // Main accumulation: per k, 4 row-pairs x 4 codes = 16 f32x2 FMAs.
        #pragma unroll 8
        for (int k = 0; k < EMBED_DIM; k++) {
            unsigned long long a2[4];
            #pragma unroll
            for (int p = 0; p < 4; p++)
                a2[p] = *(const unsigned long long*)(&xs[k][ty * 8 + 2 * p]);
            unsigned long long b2[4];
            #pragma unroll
            for (int j = 0; j < 4; j++)
                b2[j] = dup2(cs[k][tx + 16 * j]);
            #pragma unroll
            for (int j = 0; j < 4; j++)
                #pragma unroll
                for (int p = 0; p < 4; p++)
                    fma2(acc2[p][j], a2[p], b2[j]);
        }

        // Epilogue: score = c2 - 2*dot, running top-2 (ascending codes per thread).
        #pragma unroll
        for (int j = 0; j < 4; j++) {
            int code = c0 + tx + 16 * j;
            #pragma unroll
            for (int p = 0; p < 4; p++) {
                float lo, hi;
                unpack2(acc2[p][j], lo, hi);
                acc2[p][j] = 0ull;
                float d0 = fmaf(-2.0f, lo, c2v[j]);
                float d1 = fmaf(-2.0f, hi, c2v[j]);
                int r0 = 2 * p, r1 = 2 * p + 1;
                if (d0 < v1[r0]) { v2[r0] = v1[r0]; i2[r0] = i1[r0]; v1[r0] = d0; i1[r0] = code; }
                else if (d0 < v2[r0]) { v2[r0] = d0; i2[r0] = code; }
                if (d1 < v1[r1]) { v2[r1] = v1[r1]; i2[r1] = i1[r1]; v1[r1] = d1; i1[r1] = code; }
                else if (d1 < v2[r1]) { v2[r1] = d1; i2[r1] = code; }
            }
        }
    }

    // Reduce top-2 across the 16 code-lanes of each half-warp.
    #pragma unroll
    for (int off = 1; off < 16; off <<= 1) {
        #pragma unroll
        for (int i = 0; i < 8; i++) {
            float ov1 = __shfl_xor_sync(0xffffffff, v1[i], off);
            int   oi1 = __shfl_xor_sync(0xffffffff, i1[i], off);
            float ov2 = __shfl_xor_sync(0xffffffff, v2[i], off);
            int   oi2 = __shfl_xor_sync(0xffffffff, i2[i], off);
            if (ov1 < v1[i] || (ov1 == v1[i] && oi1 < i1[i])) {
                float nv2; int ni2;
                if (v1[i] < ov2 || (v1[i] == ov2 && i1[i] < oi2)) { nv2 = v1[i]; ni2 = i1[i]; }
                else                                              { nv2 = ov2;  ni2 = oi2;  }
                v1[i] = ov1; i1[i] = oi1; v2[i] = nv2; i2[i] = ni2;
            } else {
                if (ov1 < v2[i] || (ov1 == v2[i] && oi1 < i2[i])) { v2[i] = ov1; i2[i] = oi1; }
            }
        }
    }

    if (tx == 0) {
        #pragma unroll
        for (int i = 0; i < 8; i++) {
            int pair = (row0 + ty * 8 + i) * NUM_CODES + n;
            g_i1[pair] = i1[i];
            g_i2[pair] = i2[i];
            g_v1[pair] = v1[i];
            g_v2[pair] = v2[i];
        }
    }
}

// ---------------------------------------------------------------------------
// Kernel 1.5: refine near-ties. Exact fp64 distances for the top-2 candidates;
// if the exact gap is inside the reference's rounding band (TIE_EPS), emulate
// the reference's rounded tie -> argmin picks the LOWER index. Otherwise the
// exact winner (== fp32 winner) stands.
// One warp per (b,n) pair; 8 warps per CTA.
// ---------------------------------------------------------------------------
__global__ void __launch_bounds__(256)
refine_kernel(const float* __restrict__ x, const float* __restrict__ cb) {
    const int warp = threadIdx.x >> 5;
    const int lane = threadIdx.x & 31;
    const int pair = blockIdx.x * 8 + warp;
    if (pair >= NPAIR) return;

    const int ia = g_i1[pair];
    const int ib = g_i2[pair];
    const float va = g_v1[pair];
    const float vb = g_v2[pair];

    int win = ia;
    if (vb - va < 0.05f) {
        const int b = pair >> 4;
        const int n = pair & 15;
        const float* xr = x  + (size_t)b * (NUM_CODES * EMBED_DIM) + n * EMBED_DIM;
        const float* ca = cb + ((size_t)n * BOOK_SIZE + ia) * EMBED_DIM;
        const float* cc = cb + ((size_t)n * BOOK_SIZE + ib) * EMBED_DIM;

        // Exact (fp64) score difference terms: d = c2 - 2*xc  (x2 cancels)
        double da = 0.0, db = 0.0;
        #pragma unroll
        for (int t = 0; t < 2; t++) {
            int k = lane + 32 * t;
            double xv = (double)xr[k];
            double av = (double)ca[k];
            double bv = (double)cc[k];
            da += av * av - 2.0 * xv * av;
            db += bv * bv - 2.0 * xv * bv;
        }
        #pragma unroll
        for (int off = 16; off >= 1; off >>= 1) {
            da += __shfl_xor_sync(0xffffffff, da, off);
            db += __shfl_xor_sync(0xffffffff, db, off);
        }

        double gap = da - db;  // >0 means ib is the exact winner
        if (gap > TIE_EPS) {
            win = ib;                      // clear exact winner
        } else if (gap >= -TIE_EPS) {
            win = (ia < ib) ? ia : ib;     // reference-rounding tie -> lower index
        }                                   // else win = ia (clear)
    }

    if (lane == 0) g_idx[pair] = win;
}

// ---------------------------------------------------------------------------
// Kernel 2: write outputs. One CTA (256 thr) per (b,n) pair.
//   out[0 .. CW_ELEMS)        : cw_embed  [B][NC*D]
//   out[CW_ELEMS .. +B*NC*BS) : one_hot   [B][NC][BS]
// ---------------------------------------------------------------------------
__global__ void write_kernel(const float* __restrict__ cb, float* __restrict__ out) {
    const int bn = blockIdx.x;
    const int b  = bn >> 4;
    const int n  = bn & 15;
    const int t  = threadIdx.x;
    const int idx = g_idx[bn];

    // one-hot row: 1024 floats = 256 float4, one per thread
    float* oh = out + CW_ELEMS + (size_t)bn * BOOK_SIZE;
    float4 v = make_float4(0.f, 0.f, 0.f, 0.f);
    int k0 = t * 4;
    if (idx >= k0 && idx < k0 + 4) ((float*)&v)[idx - k0] = 1.0f;
    *(float4*)(oh + k0) = v;

    // codeword gather: 64 floats = 16 float4 by threads 0..15
    if (t < 16) {
        float4 w = *(const float4*)(cb + ((size_t)n * BOOK_SIZE + idx) * EMBED_DIM + t * 4);
        *(float4*)(out + (size_t)b * (NUM_CODES * EMBED_DIM) + n * EMBED_DIM + t * 4) = w;
    }
}

// ---------------------------------------------------------------------------
extern "C" void kernel_launch(void* const* d_in, const int* in_sizes, int n_in,
                              void* d_out, int out_size) {
    const float* x  = (const float*)d_in[0];
    const float* cb = (const float*)d_in[1];
    if (n_in >= 2 && in_sizes[0] == NUM_CODES * BOOK_SIZE * EMBED_DIM) {
        const float* tmp = x; x = cb; cb = tmp;
    }
    float* out = (float*)d_out;

    c2_kernel<<<(NUM_CODES * BOOK_SIZE + 255) / 256, 256>>>(cb);

    dim3 g1(BATCH / MB, NUM_CODES);
    argmin_kernel<<<g1, 256>>>(x, cb);

    refine_kernel<<<NPAIR / 8, 256>>>(x, cb);

    write_kernel<<<NPAIR, 256>>>(cb, out);
}

// round 6
// speedup vs baseline: 1.1738x; 1.1738x over previous
#include <cuda_runtime.h>
#include <cuda_bf16.h>

// Problem constants
#define BATCH     8192
#define NUM_CODES 16
#define BOOK_SIZE 1024
#define EMBED_DIM 64

// Tiling
#define MB    128   // x rows per CTA
#define CHUNK 64    // codebook rows per smem tile

#define NPAIR (BATCH * NUM_CODES)
#define CW_ELEMS ((size_t)BATCH * NUM_CODES * EMBED_DIM)   // 8,388,608

// Near-tie band on EXACT distance gap (ulp(128) = 1.53e-5; reference noise <~3 ulp)
#define TIE_EPS 4e-5

// Scratch (device globals; no allocation allowed)
__device__ float g_c2 [NUM_CODES * BOOK_SIZE];
__device__ int   g_i1 [NPAIR];
__device__ int   g_i2 [NPAIR];
__device__ float g_v1 [NPAIR];
__device__ float g_v2 [NPAIR];
__device__ int   g_idx[NPAIR];

// ---------------------------------------------------------------------------
// f32x2 packed helpers (2 fp32 MACs per instruction on the fma pipe)
// ---------------------------------------------------------------------------
__device__ __forceinline__ void fma2(unsigned long long& acc,
                                     unsigned long long a,
                                     unsigned long long b) {
    asm("fma.rn.f32x2 %0, %1, %2, %0;" : "+l"(acc) : "l"(a), "l"(b));
}
__device__ __forceinline__ unsigned long long dup2(float v) {
    unsigned long long r;
    asm("mov.b64 %0, {%1, %1};" : "=l"(r) : "f"(v));
    return r;
}
__device__ __forceinline__ void unpack2(unsigned long long v, float& lo, float& hi) {
    asm("mov.b64 {%0, %1}, %2;" : "=f"(lo), "=f"(hi) : "l"(v));
}

// ---------------------------------------------------------------------------
// Kernel 0: codebook squared norms (ranking only; refine re-derives exact
// values for borderline pairs, so summation order is uncritical).
// ---------------------------------------------------------------------------
__global__ void c2_kernel(const float* __restrict__ cb) {
    int code = blockIdx.x * blockDim.x + threadIdx.x;
    if (code < NUM_CODES * BOOK_SIZE) {
        const float4* p = (const float4*)(cb + (size_t)code * EMBED_DIM);
        float s = 0.f;
        #pragma unroll
        for (int i = 0; i < EMBED_DIM / 4; i++) {
            float4 v = p[i];
            s += v.x * v.x + v.y * v.y + v.z * v.z + v.w * v.w;
        }
        g_c2[code] = s;
    }
}

// ---------------------------------------------------------------------------
// Kernel 1: top-2 argmin over (c2 - 2*dot)  [x2 is row-constant -> dropped].
// Grid (BATCH/MB, NUM_CODES), 256 threads.
//   tx = tid & 15  -> code lane; this thread handles codes c0 + tx*4 + j,
//                     j in [0,4)  (CONSECUTIVE -> one LDS.128 per k)
//   ty = tid >> 4  -> row group (rows ty*8 .. ty*8+7, paired for f32x2;
//                     loaded as two LDS.128 per k)
// Per k per warp: 16 FFMA2 (32-cycle issue window) + 3 LDS.128 + 4 MOV.
// ---------------------------------------------------------------------------
__global__ void __launch_bounds__(256)
argmin_kernel(const float* __restrict__ x, const float* __restrict__ cb) {
    __shared__ float xs[EMBED_DIM][MB];      // 32 KB, transposed
    __shared__ float cs[EMBED_DIM][CHUNK];   // 16 KB, transposed

    const int tid  = threadIdx.x;
    const int tx   = tid & 15;
    const int ty   = tid >> 4;
    const int n    = blockIdx.y;
    const int row0 = blockIdx.x * MB;

    const float* xbase = x  + (size_t)row0 * (NUM_CODES * EMBED_DIM) + n * EMBED_DIM;
    const float* cbase = cb + (size_t)n * (BOOK_SIZE * EMBED_DIM);

    // Load x tile (transposed). 128 rows x 16 float4 columns.
    for (int it = tid; it < MB * (EMBED_DIM / 4); it += 256) {
        int r  = it >> 4;
        int c4 = it & 15;
        float4 v = *(const float4*)(xbase + (size_t)r * (NUM_CODES * EMBED_DIM) + c4 * 4);
        xs[c4 * 4 + 0][r] = v.x;
        xs[c4 * 4 + 1][r] = v.y;
        xs[c4 * 4 + 2][r] = v.z;
        xs[c4 * 4 + 3][r] = v.w;
    }

    float v1[8], v2[8];
    int   i1[8], i2[8];
    #pragma unroll
    for (int i = 0; i < 8; i++) {
        v1[i] = 3.4e38f; v2[i] = 3.4e38f; i1[i] = 0; i2[i] = 0;
    }

    unsigned long long acc2[4][4];   // [row-pair p][code j]
    #pragma unroll
    for (int p = 0; p < 4; p++)
        #pragma unroll
        for (int j = 0; j < 4; j++) acc2[p][j] = 0ull;

    for (int c0 = 0; c0 < BOOK_SIZE; c0 += CHUNK) {
        __syncthreads();
        // Load code tile (transposed)
        for (int it = tid; it < CHUNK * (EMBED_DIM / 4); it += 256) {
            int r  = it >> 4;
            int c4 = it & 15;
            float4 v = *(const float4*)(cbase + (size_t)(c0 + r) * EMBED_DIM + c4 * 4);
            cs[c4 * 4 + 0][r] = v.x;
            cs[c4 * 4 + 1][r] = v.y;
            cs[c4 * 4 + 2][r] = v.z;
            cs[c4 * 4 + 3][r] = v.w;
        }
        __syncthreads();

        float c2v[4];
        #pragma unroll
        for (int j = 0; j < 4; j++)
            c2v[j] = __ldg(&g_c2[n * BOOK_SIZE + c0 + tx * 4 + j]);

        // Main accumulation: per k, 4 row-pairs x 4 codes = 16 f32x2 FMAs,
        // fed by 2 LDS.128 (x rows) + 1 LDS.128 (codes) + 4 dup MOVs.
        #pragma unroll 8
        for (int k = 0; k < EMBED_DIM; k++) {
            ulonglong2 A0 = *(const ulonglong2*)(&xs[k][ty * 8]);      // rows 0-3
            ulonglong2 A1 = *(const ulonglong2*)(&xs[k][ty * 8 + 4]);  // rows 4-7
            unsigned long long a2[4] = { A0.x, A0.y, A1.x, A1.y };
            float4 cv = *(const float4*)(&cs[k][tx * 4]);
            unsigned long long b2[4];
            b2[0] = dup2(cv.x);
            b2[1] = dup2(cv.y);
            b2[2] = dup2(cv.z);
            b2[3] = dup2(cv.w);
            #pragma unroll
            for (int j = 0; j < 4; j++)
                #pragma unroll
                for (int p = 0; p < 4; p++)
                    fma2(acc2[p][j], a2[p], b2[j]);
        }

        // Epilogue: score = c2 - 2*dot, running top-2 (codes ascending per thread).
        #pragma unroll
        for (int j = 0; j < 4; j++) {
            int code = c0 + tx * 4 + j;
            #pragma unroll
            for (int p = 0; p < 4; p++) {
                float lo, hi;
                unpack2(acc2[p][j], lo, hi);
                acc2[p][j] = 0ull;
                float d0 = fmaf(-2.0f, lo, c2v[j]);
                float d1 = fmaf(-2.0f, hi, c2v[j]);
                int r0 = 2 * p, r1 = 2 * p + 1;
                if (d0 < v1[r0]) { v2[r0] = v1[r0]; i2[r0] = i1[r0]; v1[r0] = d0; i1[r0] = code; }
                else if (d0 < v2[r0]) { v2[r0] = d0; i2[r0] = code; }
                if (d1 < v1[r1]) { v2[r1] = v1[r1]; i2[r1] = i1[r1]; v1[r1] = d1; i1[r1] = code; }
                else if (d1 < v2[r1]) { v2[r1] = d1; i2[r1] = code; }
            }
        }
    }

    // Reduce top-2 across the 16 code-lanes of each half-warp.
    #pragma unroll
    for (int off = 1; off < 16; off <<= 1) {
        #pragma unroll
        for (int i = 0; i < 8; i++) {
            float ov1 = __shfl_xor_sync(0xffffffff, v1[i], off);
            int   oi1 = __shfl_xor_sync(0xffffffff, i1[i], off);
            float ov2 = __shfl_xor_sync(0xffffffff, v2[i], off);
            int   oi2 = __shfl_xor_sync(0xffffffff, i2[i], off);
            if (ov1 < v1[i] || (ov1 == v1[i] && oi1 < i1[i])) {
                float nv2; int ni2;
                if (v1[i] < ov2 || (v1[i] == ov2 && i1[i] < oi2)) { nv2 = v1[i]; ni2 = i1[i]; }
                else                                              { nv2 = ov2;  ni2 = oi2;  }
                v1[i] = ov1; i1[i] = oi1; v2[i] = nv2; i2[i] = ni2;
            } else {
                if (ov1 < v2[i] || (ov1 == v2[i] && oi1 < i2[i])) { v2[i] = ov1; i2[i] = oi1; }
            }
        }
    }

    if (tx == 0) {
        #pragma unroll
        for (int i = 0; i < 8; i++) {
            int pair = (row0 + ty * 8 + i) * NUM_CODES + n;
            g_i1[pair] = i1[i];
            g_i2[pair] = i2[i];
            g_v1[pair] = v1[i];
            g_v2[pair] = v2[i];
        }
    }
}

// ---------------------------------------------------------------------------
// Kernel 1.5: refine near-ties. Exact fp64 distances for the top-2 candidates;
// inside the reference's rounding band (TIE_EPS) emulate the rounded tie ->
// argmin picks the LOWER index. Otherwise the exact winner stands.
// One warp per (b,n) pair; 8 warps per CTA.  (UNCHANGED from passing R5.)
// ---------------------------------------------------------------------------
__global__ void __launch_bounds__(256)
refine_kernel(const float* __restrict__ x, const float* __restrict__ cb) {
    const int warp = threadIdx.x >> 5;
    const int lane = threadIdx.x & 31;
    const int pair = blockIdx.x * 8 + warp;
    if (pair >= NPAIR) return;

    const int ia = g_i1[pair];
    const int ib = g_i2[pair];
    const float va = g_v1[pair];
    const float vb = g_v2[pair];

    int win = ia;
    if (vb - va < 0.05f) {
        const int b = pair >> 4;
        const int n = pair & 15;
        const float* xr = x  + (size_t)b * (NUM_CODES * EMBED_DIM) + n * EMBED_DIM;
        const float* ca = cb + ((size_t)n * BOOK_SIZE + ia) * EMBED_DIM;
        const float* cc = cb + ((size_t)n * BOOK_SIZE + ib) * EMBED_DIM;

        double da = 0.0, db = 0.0;
        #pragma unroll
        for (int t = 0; t < 2; t++) {
            int k = lane + 32 * t;
            double xv = (double)xr[k];
            double av = (double)ca[k];
            double bv = (double)cc[k];
            da += av * av - 2.0 * xv * av;
            db += bv * bv - 2.0 * xv * bv;
        }
        #pragma unroll
        for (int off = 16; off >= 1; off >>= 1) {
            da += __shfl_xor_sync(0xffffffff, da, off);
            db += __shfl_xor_sync(0xffffffff, db, off);
        }

        double gap = da - db;  // >0 means ib is the exact winner
        if (gap > TIE_EPS) {
            win = ib;
        } else if (gap >= -TIE_EPS) {
            win = (ia < ib) ? ia : ib;     // reference-rounding tie -> lower index
        }
    }

    if (lane == 0) g_idx[pair] = win;
}

// ---------------------------------------------------------------------------
// Kernel 2: write outputs. ONE WARP per (b,n) pair, 8 pairs per CTA.
//   out[0 .. CW_ELEMS)        : cw_embed  [B][NC*D]
//   out[CW_ELEMS .. +B*NC*BS) : one_hot   [B][NC][BS]
// ---------------------------------------------------------------------------
__global__ void __launch_bounds__(256)
write_kernel(const float* __restrict__ cb, float* __restrict__ out) {
    const int warp = threadIdx.x >> 5;
    const int lane = threadIdx.x & 31;
    const int bn   = blockIdx.x * 8 + warp;
    const int b  = bn >> 4;
    const int n  = bn & 15;
    const int idx = g_idx[bn];

    // one-hot row: 1024 floats = 256 float4; 8 coalesced float4 per lane
    float4* oh = (float4*)(out + CW_ELEMS + (size_t)bn * BOOK_SIZE);
    const int hot4 = idx >> 2;          // which float4 holds the 1.0
    #pragma unroll
    for (int i = 0; i < 8; i++) {
        int f4 = i * 32 + lane;
        float4 v = make_float4(0.f, 0.f, 0.f, 0.f);
        if (f4 == hot4) ((float*)&v)[idx & 3] = 1.0f;
        oh[f4] = v;
    }

    // codeword gather: 64 floats = 16 float4 by lanes 0..15
    if (lane < 16) {
        float4 w = *(const float4*)(cb + ((size_t)n * BOOK_SIZE + idx) * EMBED_DIM + lane * 4);
        *(float4*)(out + (size_t)b * (NUM_CODES * EMBED_DIM) + n * EMBED_DIM + lane * 4) = w;
    }
}

// ---------------------------------------------------------------------------
extern "C" void kernel_launch(void* const* d_in, const int* in_sizes, int n_in,
                              void* d_out, int out_size) {
    const float* x  = (const float*)d_in[0];
    const float* cb = (const float*)d_in[1];
    if (n_in >= 2 && in_sizes[0] == NUM_CODES * BOOK_SIZE * EMBED_DIM) {
        const float* tmp = x; x = cb; cb = tmp;
    }
    float* out = (float*)d_out;

    c2_kernel<<<(NUM_CODES * BOOK_SIZE + 255) / 256, 256>>>(cb);

    dim3 g1(BATCH / MB, NUM_CODES);
    argmin_kernel<<<g1, 256>>>(x, cb);

    refine_kernel<<<NPAIR / 8, 256>>>(x, cb);

    write_kernel<<<NPAIR / 8, 256>>>(cb, out);
}

// round 7
// speedup vs baseline: 1.6202x; 1.3803x over previous
#include <cuda_runtime.h>
#include <cuda_bf16.h>

// Problem constants
#define BATCH     8192
#define NUM_CODES 16
#define BOOK_SIZE 1024
#define EMBED_DIM 64

// Tiling
#define MB     128   // x rows per CTA
#define CHUNK  32    // codebook rows per smem tile
#define CS_PAD 40    // cs row stride (40 % 32 == 8 -> conflict-free B-frag reads)

#define NPAIR (BATCH * NUM_CODES)
#define CW_ELEMS ((size_t)BATCH * NUM_CODES * EMBED_DIM)   // 8,388,608

// Near-tie band on EXACT distance gap (proven in R5 pass — do not change)
#define TIE_EPS 4e-5
// tf32 ranking noise gate for fp64 refine (noise sigma ~0.016 -> 0.15 = 9 sigma)
#define MARGIN  0.15f

// Scratch (device globals; no allocation allowed)
__device__ float g_c2  [NUM_CODES * BOOK_SIZE];
__device__ int   g_cand[(size_t)NPAIR * 12];
__device__ float g_cval[(size_t)NPAIR * 12];
__device__ int   g_idx [NPAIR];

// ---------------------------------------------------------------------------
__device__ __forceinline__ unsigned int f2tf32(float f) {
    unsigned int r;
    asm("cvt.rna.tf32.f32 %0, %1;" : "=r"(r) : "f"(f));
    return r;
}
__device__ __forceinline__ void mma_tf32(float& d0, float& d1, float& d2, float& d3,
                                         unsigned int a0, unsigned int a1,
                                         unsigned int a2, unsigned int a3,
                                         unsigned int b0, unsigned int b1) {
    asm("mma.sync.aligned.m16n8k8.row.col.f32.tf32.tf32.f32 "
        "{%0,%1,%2,%3}, {%4,%5,%6,%7}, {%8,%9}, {%0,%1,%2,%3};"
        : "+f"(d0), "+f"(d1), "+f"(d2), "+f"(d3)
        : "r"(a0), "r"(a1), "r"(a2), "r"(a3), "r"(b0), "r"(b1));
}

// ---------------------------------------------------------------------------
// Kernel 0: codebook squared norms (ranking only; refine re-derives exact
// values for borderline pairs).
// ---------------------------------------------------------------------------
__global__ void c2_kernel(const float* __restrict__ cb) {
    int code = blockIdx.x * blockDim.x + threadIdx.x;
    if (code < NUM_CODES * BOOK_SIZE) {
        const float4* p = (const float4*)(cb + (size_t)code * EMBED_DIM);
        float s = 0.f;
        #pragma unroll
        for (int i = 0; i < EMBED_DIM / 4; i++) {
            float4 v = p[i];
            s += v.x * v.x + v.y * v.y + v.z * v.z + v.w * v.w;
        }
        g_c2[code] = s;
    }
}

// ---------------------------------------------------------------------------
// Kernel 1: tf32 tensor-core distance ranking, per-thread top-3 candidates.
// Grid (BATCH/MB, NUM_CODES), 256 threads = 8 warps; warp w owns rows
// [w*16, w*16+16) of the CTA's 128 rows and scans all 1024 codes in
// m16n8k8 tiles. score = c2 - 2*dot (x2 row-constant, dropped).
// Fragment ownership (g = lane>>2, t = lane&3):
//   D: rows {g, g+8}, cols {2t, 2t+1} of each 8-code tile.
// ---------------------------------------------------------------------------
__global__ void __launch_bounds__(256)
argmin_kernel(const float* __restrict__ x, const float* __restrict__ cb) {
    __shared__ float xs[EMBED_DIM][MB];            // 32 KB, transposed x tile
    __shared__ float cs[EMBED_DIM * CS_PAD];       // 10 KB, transposed code tile

    const int tid  = threadIdx.x;
    const int w    = tid >> 5;
    const int lane = tid & 31;
    const int g    = lane >> 2;
    const int t    = lane & 3;
    const int n    = blockIdx.y;
    const int row0 = blockIdx.x * MB;
    const int rw   = w * 16;   // warp's row base within tile

    const float* xbase = x  + (size_t)row0 * (NUM_CODES * EMBED_DIM) + n * EMBED_DIM;
    const float* cbase = cb + (size_t)n * (BOOK_SIZE * EMBED_DIM);
    const float* c2b   = &g_c2[n * BOOK_SIZE];

    // Load x tile (transposed). 128 rows x 16 float4 columns, coalesced.
    for (int it = tid; it < MB * (EMBED_DIM / 4); it += 256) {
        int r  = it >> 4;
        int c4 = it & 15;
        float4 v = *(const float4*)(xbase + (size_t)r * (NUM_CODES * EMBED_DIM) + c4 * 4);
        xs[c4 * 4 + 0][r] = v.x;
        xs[c4 * 4 + 1][r] = v.y;
        xs[c4 * 4 + 2][r] = v.z;
        xs[c4 * 4 + 3][r] = v.w;
    }
    __syncthreads();

    // A fragments for the full K=64 (8 k-steps), loaded once, kept as tf32.
    unsigned int a[8][4];
    #pragma unroll
    for (int s = 0; s < 8; s++) {
        a[s][0] = f2tf32(xs[8 * s + t    ][rw + g    ]);
        a[s][1] = f2tf32(xs[8 * s + t    ][rw + g + 8]);
        a[s][2] = f2tf32(xs[8 * s + t + 4][rw + g    ]);
        a[s][3] = f2tf32(xs[8 * s + t + 4][rw + g + 8]);
    }

    // Per-thread top-3 for each of the 2 rows this thread owns.
    float rv[2][3];
    int   ri[2][3];
    #pragma unroll
    for (int h = 0; h < 2; h++)
        #pragma unroll
        for (int j = 0; j < 3; j++) { rv[h][j] = 3.4e38f; ri[h][j] = 0; }

    for (int c0 = 0; c0 < BOOK_SIZE; c0 += CHUNK) {
        __syncthreads();
        // Load code tile transposed into padded cs: cs[k*CS_PAD + code].
        // it: r = code (coalesced store banks), c4 = float4 column of k.
        for (int it = tid; it < CHUNK * (EMBED_DIM / 4); it += 256) {
            int r  = it & (CHUNK - 1);
            int c4 = it >> 5;
            float4 v = *(const float4*)(cbase + (size_t)(c0 + r) * EMBED_DIM + c4 * 4);
            cs[(c4 * 4 + 0) * CS_PAD + r] = v.x;
            cs[(c4 * 4 + 1) * CS_PAD + r] = v.y;
            cs[(c4 * 4 + 2) * CS_PAD + r] = v.z;
            cs[(c4 * 4 + 3) * CS_PAD + r] = v.w;
        }
        __syncthreads();

        #pragma unroll
        for (int tc = 0; tc < CHUNK / 8; tc++) {
            const int cbs = tc * 8;            // tile base within chunk
            const int cg  = c0 + cbs;          // global tile base

            // B fragments: b0 = B[t][g], b1 = B[t+4][g]  (k-major rows)
            unsigned int bb[8][2];
            #pragma unroll
            for (int s = 0; s < 8; s++) {
                bb[s][0] = f2tf32(cs[(8 * s + t    ) * CS_PAD + cbs + g]);
                bb[s][1] = f2tf32(cs[(8 * s + t + 4) * CS_PAD + cbs + g]);
            }

            float d0 = 0.f, d1 = 0.f, d2 = 0.f, d3 = 0.f;
            #pragma unroll
            for (int s = 0; s < 8; s++)
                mma_tf32(d0, d1, d2, d3, a[s][0], a[s][1], a[s][2], a[s][3],
                         bb[s][0], bb[s][1]);

            // distances for this thread's 2 cols x 2 rows
            float2 c2v = *(const float2*)(c2b + cg + 2 * t);
            int code0 = cg + 2 * t, code1 = code0 + 1;

            float e;
            // row g (h=0): d0 (code0), d1 (code1)
            e = fmaf(-2.0f, d0, c2v.x);
            if (e < rv[0][0]) { rv[0][2]=rv[0][1]; ri[0][2]=ri[0][1]; rv[0][1]=rv[0][0]; ri[0][1]=ri[0][0]; rv[0][0]=e; ri[0][0]=code0; }
            else if (e < rv[0][1]) { rv[0][2]=rv[0][1]; ri[0][2]=ri[0][1]; rv[0][1]=e; ri[0][1]=code0; }
            else if (e < rv[0][2]) { rv[0][2]=e; ri[0][2]=code0; }
            e = fmaf(-2.0f, d1, c2v.y);
            if (e < rv[0][0]) { rv[0][2]=rv[0][1]; ri[0][2]=ri[0][1]; rv[0][1]=rv[0][0]; ri[0][1]=ri[0][0]; rv[0][0]=e; ri[0][0]=code1; }
            else if (e < rv[0][1]) { rv[0][2]=rv[0][1]; ri[0][2]=ri[0][1]; rv[0][1]=e; ri[0][1]=code1; }
            else if (e < rv[0][2]) { rv[0][2]=e; ri[0][2]=code1; }
            // row g+8 (h=1): d2 (code0), d3 (code1)
            e = fmaf(-2.0f, d2, c2v.x);
            if (e < rv[1][0]) { rv[1][2]=rv[1][1]; ri[1][2]=ri[1][1]; rv[1][1]=rv[1][0]; ri[1][1]=ri[1][0]; rv[1][0]=e; ri[1][0]=code0; }
            else if (e < rv[1][1]) { rv[1][2]=rv[1][1]; ri[1][2]=ri[1][1]; rv[1][1]=e; ri[1][1]=code0; }
            else if (e < rv[1][2]) { rv[1][2]=e; ri[1][2]=code0; }
            e = fmaf(-2.0f, d3, c2v.y);
            if (e < rv[1][0]) { rv[1][2]=rv[1][1]; ri[1][2]=ri[1][1]; rv[1][1]=rv[1][0]; ri[1][1]=ri[1][0]; rv[1][0]=e; ri[1][0]=code1; }
            else if (e < rv[1][1]) { rv[1][2]=rv[1][1]; ri[1][2]=ri[1][1]; rv[1][1]=e; ri[1][1]=code1; }
            else if (e < rv[1][2]) { rv[1][2]=e; ri[1][2]=code1; }
        }
    }

    // Emit candidates: 4 quad-lanes x top-3 = 12 per row.
    #pragma unroll
    for (int h = 0; h < 2; h++) {
        int row  = row0 + rw + g + 8 * h;
        size_t base = (size_t)(row * NUM_CODES + n) * 12 + t * 3;
        #pragma unroll
        for (int j = 0; j < 3; j++) {
            g_cand[base + j] = ri[h][j];
            g_cval[base + j] = rv[h][j];
        }
    }
}

// ---------------------------------------------------------------------------
// Kernel 1.5: resolve each pair from its 12 candidates.
// Candidates within MARGIN of the approx min get exact fp64 distances;
// among exact values, anything within TIE_EPS of the exact min emulates the
// reference's rounded tie -> lowest index wins. One warp per pair.
// ---------------------------------------------------------------------------
__global__ void __launch_bounds__(256)
refine_kernel(const float* __restrict__ x, const float* __restrict__ cb) {
    const int warp = threadIdx.x >> 5;
    const int lane = threadIdx.x & 31;
    const int pair = blockIdx.x * 8 + warp;
    if (pair >= NPAIR) return;

    int   cand = 0;
    float val  = 3.4e38f;
    if (lane < 12) {
        cand = g_cand[(size_t)pair * 12 + lane];
        val  = g_cval[(size_t)pair * 12 + lane];
    }

    // approx min over candidates
    float vmin = val;
    #pragma unroll
    for (int off = 16; off >= 1; off >>= 1)
        vmin = fminf(vmin, __shfl_xor_sync(0xffffffffu, vmin, off));

    bool active = (lane < 12) && (val <= vmin + MARGIN);
    unsigned actmask = __ballot_sync(0xffffffffu, active);
    int win;

    if (__popc(actmask) == 1) {
        int src = __ffs(actmask) - 1;
        win = __shfl_sync(0xffffffffu, cand, src);
    } else {
        const int b = pair >> 4;
        const int n = pair & 15;
        const float* xr = x + (size_t)b * (NUM_CODES * EMBED_DIM) + n * EMBED_DIM;

        double dj = 1e300;   // lane j holds exact dist of candidate j
        for (int j = 0; j < 12; j++) {
            if (!((actmask >> j) & 1u)) continue;
            int cidx = __shfl_sync(0xffffffffu, cand, j);
            const float* cc = cb + ((size_t)n * BOOK_SIZE + cidx) * EMBED_DIM;
            double d = 0.0;
            #pragma unroll
            for (int u = 0; u < 2; u++) {
                int k = lane + 32 * u;
                double xv = (double)xr[k];
                double cv = (double)cc[k];
                d += cv * cv - 2.0 * xv * cv;
            }
            #pragma unroll
            for (int off = 16; off >= 1; off >>= 1)
                d += __shfl_xor_sync(0xffffffffu, d, off);
            if (lane == j) dj = d;
        }

        double dmin = dj;
        #pragma unroll
        for (int off = 16; off >= 1; off >>= 1)
            dmin = fmin(dmin, __shfl_xor_sync(0xffffffffu, dmin, off));

        bool elig = ((actmask >> lane) & 1u) && (lane < 12) && (dj <= dmin + TIE_EPS);
        int key = elig ? cand : 0x7fffffff;
        #pragma unroll
        for (int off = 16; off >= 1; off >>= 1)
            key = min(key, __shfl_xor_sync(0xffffffffu, key, off));
        win = key;
    }

    if (lane == 0) g_idx[pair] = win;
}

// ---------------------------------------------------------------------------
// Kernel 2: write outputs. ONE WARP per (b,n) pair, 8 pairs per CTA.
//   out[0 .. CW_ELEMS)        : cw_embed  [B][NC*D]
//   out[CW_ELEMS .. +B*NC*BS) : one_hot   [B][NC][BS]
// ---------------------------------------------------------------------------
__global__ void __launch_bounds__(256)
write_kernel(const float* __restrict__ cb, float* __restrict__ out) {
    const int warp = threadIdx.x >> 5;
    const int lane = threadIdx.x & 31;
    const int bn   = blockIdx.x * 8 + warp;
    const int b  = bn >> 4;
    const int n  = bn & 15;
    const int idx = g_idx[bn];

    // one-hot row: 1024 floats = 256 float4; 8 coalesced float4 per lane
    float4* oh = (float4*)(out + CW_ELEMS + (size_t)bn * BOOK_SIZE);
    const int hot4 = idx >> 2;
    #pragma unroll
    for (int i = 0; i < 8; i++) {
        int f4 = i * 32 + lane;
        float4 v = make_float4(0.f, 0.f, 0.f, 0.f);
        if (f4 == hot4) ((float*)&v)[idx & 3] = 1.0f;
        oh[f4] = v;
    }

    // codeword gather: 64 floats = 16 float4 by lanes 0..15
    if (lane < 16) {
        float4 w = *(const float4*)(cb + ((size_t)n * BOOK_SIZE + idx) * EMBED_DIM + lane * 4);
        *(float4*)(out + (size_t)b * (NUM_CODES * EMBED_DIM) + n * EMBED_DIM + lane * 4) = w;
    }
}

// ---------------------------------------------------------------------------
extern "C" void kernel_launch(void* const* d_in, const int* in_sizes, int n_in,
                              void* d_out, int out_size) {
    const float* x  = (const float*)d_in[0];
    const float* cb = (const float*)d_in[1];
    if (n_in >= 2 && in_sizes[0] == NUM_CODES * BOOK_SIZE * EMBED_DIM) {
        const float* tmp = x; x = cb; cb = tmp;
    }
    float* out = (float*)d_out;

    c2_kernel<<<(NUM_CODES * BOOK_SIZE + 255) / 256, 256>>>(cb);

    dim3 g1(BATCH / MB, NUM_CODES);
    argmin_kernel<<<g1, 256>>>(x, cb);

    refine_kernel<<<NPAIR / 8, 256>>>(x, cb);

    write_kernel<<<NPAIR / 8, 256>>>(cb, out);
}

// round 8
// speedup vs baseline: 1.8288x; 1.1288x over previous
#include <cuda_runtime.h>
#include <cuda_bf16.h>

// Problem constants
#define BATCH     8192
#define NUM_CODES 16
#define BOOK_SIZE 1024
#define EMBED_DIM 64

// Tiling
#define MB     128   // x rows per CTA
#define CHUNK  32    // codebook rows per smem tile

#define NPAIR (BATCH * NUM_CODES)
#define CW_ELEMS ((size_t)BATCH * NUM_CODES * EMBED_DIM)   // 8,388,608

// Near-tie band on EXACT distance gap (proven in R5 pass — do not change)
#define TIE_EPS 4e-5
// tf32 ranking noise gate for fp64 refine (noise sigma ~0.016 -> 0.15 = 9 sigma)
#define MARGIN  0.15f

// B-fragment smem: 4 q-blocks of (CHUNK*4 + 1) uint4  (+1 pads fill banks)
#define QBLK (CHUNK * 4 + 1)

// Scratch (device globals; no allocation allowed)
__device__ float g_c2  [NUM_CODES * BOOK_SIZE];
__device__ int   g_cand[(size_t)NPAIR * 12];
__device__ float g_cval[(size_t)NPAIR * 12];
__device__ int   g_idx [NPAIR];

// ---------------------------------------------------------------------------
__device__ __forceinline__ unsigned int f2tf32(float f) {
    unsigned int r;
    asm("cvt.rna.tf32.f32 %0, %1;" : "=r"(r) : "f"(f));
    return r;
}
__device__ __forceinline__ void mma_tf32(float& d0, float& d1, float& d2, float& d3,
                                         unsigned int a0, unsigned int a1,
                                         unsigned int a2, unsigned int a3,
                                         unsigned int b0, unsigned int b1) {
    asm("mma.sync.aligned.m16n8k8.row.col.f32.tf32.tf32.f32 "
        "{%0,%1,%2,%3}, {%4,%5,%6,%7}, {%8,%9}, {%0,%1,%2,%3};"
        : "+f"(d0), "+f"(d1), "+f"(d2), "+f"(d3)
        : "r"(a0), "r"(a1), "r"(a2), "r"(a3), "r"(b0), "r"(b1));
}

// ---------------------------------------------------------------------------
// Kernel 0: codebook squared norms (ranking only; refine re-derives exact
// values for borderline pairs).
// ---------------------------------------------------------------------------
__global__ void c2_kernel(const float* __restrict__ cb) {
    int code = blockIdx.x * blockDim.x + threadIdx.x;
    if (code < NUM_CODES * BOOK_SIZE) {
        const float4* p = (const float4*)(cb + (size_t)code * EMBED_DIM);
        float s = 0.f;
        #pragma unroll
        for (int i = 0; i < EMBED_DIM / 4; i++) {
            float4 v = p[i];
            s += v.x * v.x + v.y * v.y + v.z * v.z + v.w * v.w;
        }
        g_c2[code] = s;
    }
}

// ---------------------------------------------------------------------------
// Kernel 1: tf32 tensor-core distance ranking, per-thread top-3 candidates.
// Grid (BATCH/MB, NUM_CODES), 256 threads = 8 warps; warp w owns rows
// [w*16, w*16+16). score = c2 - 2*dot (x2 row-constant, dropped).
// B data is pre-converted to tf32 at tile-fill time and stored in fragment
// order: csf uint4 at index128 = q*QBLK + code*4 + t  holds k4 = 4q+inner,
// i.e. k = 16q + 4*inner + t. Thread (g,t) fetches its whole K=64 B-fragment
// for codes {tile base + g} with 4 LDS.128 (bank-conflict-free).
// ---------------------------------------------------------------------------
__global__ void __launch_bounds__(256)
argmin_kernel(const float* __restrict__ x, const float* __restrict__ cb) {
    __shared__ float xs[EMBED_DIM][MB];        // 32 KB, transposed x tile
    __shared__ uint4 csf[4 * QBLK];            // ~8.3 KB, tf32 B fragments

    const int tid  = threadIdx.x;
    const int w    = tid >> 5;
    const int lane = tid & 31;
    const int g    = lane >> 2;
    const int t    = lane & 3;
    const int n    = blockIdx.y;
    const int row0 = blockIdx.x * MB;
    const int rw   = w * 16;   // warp's row base within tile

    const float* xbase = x  + (size_t)row0 * (NUM_CODES * EMBED_DIM) + n * EMBED_DIM;
    const float* cbase = cb + (size_t)n * (BOOK_SIZE * EMBED_DIM);
    const float* c2b   = &g_c2[n * BOOK_SIZE];

    // Load x tile (transposed). 128 rows x 16 float4 columns, coalesced.
    for (int it = tid; it < MB * (EMBED_DIM / 4); it += 256) {
        int r  = it >> 4;
        int c4 = it & 15;
        float4 v = *(const float4*)(xbase + (size_t)r * (NUM_CODES * EMBED_DIM) + c4 * 4);
        xs[c4 * 4 + 0][r] = v.x;
        xs[c4 * 4 + 1][r] = v.y;
        xs[c4 * 4 + 2][r] = v.z;
        xs[c4 * 4 + 3][r] = v.w;
    }
    __syncthreads();

    // A fragments for the full K=64 (8 k-steps), loaded once, kept as tf32.
    unsigned int a[8][4];
    #pragma unroll
    for (int s = 0; s < 8; s++) {
        a[s][0] = f2tf32(xs[8 * s + t    ][rw + g    ]);
        a[s][1] = f2tf32(xs[8 * s + t    ][rw + g + 8]);
        a[s][2] = f2tf32(xs[8 * s + t + 4][rw + g    ]);
        a[s][3] = f2tf32(xs[8 * s + t + 4][rw + g + 8]);
    }

    // Per-thread top-3 for each of the 2 rows this thread owns.
    float rv[2][3];
    int   ri[2][3];
    #pragma unroll
    for (int h = 0; h < 2; h++)
        #pragma unroll
        for (int j = 0; j < 3; j++) { rv[h][j] = 3.4e38f; ri[h][j] = 0; }

    unsigned int* csf32 = (unsigned int*)csf;

    for (int c0 = 0; c0 < BOOK_SIZE; c0 += CHUNK) {
        __syncthreads();
        // Fill csf: CHUNK codes x 16 float4 columns; convert to tf32 once.
        // Element (code, k): q=k>>4, tt=k&3, inner=(k>>2)&3 ->
        //   csf32[(q*QBLK + code*4 + tt)*4 + inner]
        for (int it = tid; it < CHUNK * (EMBED_DIM / 4); it += 256) {
            int code = it >> 4;
            int c4   = it & 15;
            int q    = c4 >> 2;
            int inr  = c4 & 3;
            float4 v = *(const float4*)(cbase + (size_t)(c0 + code) * EMBED_DIM + c4 * 4);
            unsigned int base = (q * QBLK + code * 4) * 4 + inr;
            csf32[base     ] = f2tf32(v.x);   // tt=0
            csf32[base + 4 ] = f2tf32(v.y);   // tt=1
            csf32[base + 8 ] = f2tf32(v.z);   // tt=2
            csf32[base + 12] = f2tf32(v.w);   // tt=3
        }
        __syncthreads();

        #pragma unroll
        for (int tc = 0; tc < CHUNK / 8; tc++) {
            const int cbs = tc * 8;            // tile base within chunk
            const int cg  = c0 + cbs;          // global tile base
            const int code = cbs + g;

            // 4 LDS.128: q-block fragments for this thread's code.
            // Q[q] = {k4=4q, 4q+1, 4q+2, 4q+3} -> bb[s][0]=k4 even(2s), [1]=odd.
            uint4 Q0 = csf[0 * QBLK + code * 4 + t];
            uint4 Q1 = csf[1 * QBLK + code * 4 + t];
            uint4 Q2 = csf[2 * QBLK + code * 4 + t];
            uint4 Q3 = csf[3 * QBLK + code * 4 + t];

            float d0 = 0.f, d1 = 0.f, d2 = 0.f, d3 = 0.f;
            mma_tf32(d0, d1, d2, d3, a[0][0], a[0][1], a[0][2], a[0][3], Q0.x, Q0.y);
            mma_tf32(d0, d1, d2, d3, a[1][0], a[1][1], a[1][2], a[1][3], Q0.z, Q0.w);
            mma_tf32(d0, d1, d2, d3, a[2][0], a[2][1], a[2][2], a[2][3], Q1.x, Q1.y);
            mma_tf32(d0, d1, d2, d3, a[3][0], a[3][1], a[3][2], a[3][3], Q1.z, Q1.w);
            mma_tf32(d0, d1, d2, d3, a[4][0], a[4][1], a[4][2], a[4][3], Q2.x, Q2.y);
            mma_tf32(d0, d1, d2, d3, a[5][0], a[5][1], a[5][2], a[5][3], Q2.z, Q2.w);
            mma_tf32(d0, d1, d2, d3, a[6][0], a[6][1], a[6][2], a[6][3], Q3.x, Q3.y);
            mma_tf32(d0, d1, d2, d3, a[7][0], a[7][1], a[7][2], a[7][3], Q3.z, Q3.w);

            // distances for this thread's 2 cols x 2 rows
            float2 c2v = *(const float2*)(c2b + cg + 2 * t);
            int code0 = cg + 2 * t, code1 = code0 + 1;

            float e;
            e = fmaf(-2.0f, d0, c2v.x);
            if (e < rv[0][0]) { rv[0][2]=rv[0][1]; ri[0][2]=ri[0][1]; rv[0][1]=rv[0][0]; ri[0][1]=ri[0][0]; rv[0][0]=e; ri[0][0]=code0; }
            else if (e < rv[0][1]) { rv[0][2]=rv[0][1]; ri[0][2]=ri[0][1]; rv[0][1]=e; ri[0][1]=code0; }
            else if (e < rv[0][2]) { rv[0][2]=e; ri[0][2]=code0; }
            e = fmaf(-2.0f, d1, c2v.y);
            if (e < rv[0][0]) { rv[0][2]=rv[0][1]; ri[0][2]=ri[0][1]; rv[0][1]=rv[0][0]; ri[0][1]=ri[0][0]; rv[0][0]=e; ri[0][0]=code1; }
            else if (e < rv[0][1]) { rv[0][2]=rv[0][1]; ri[0][2]=ri[0][1]; rv[0][1]=e; ri[0][1]=code1; }
            else if (e < rv[0][2]) { rv[0][2]=e; ri[0][2]=code1; }
            e = fmaf(-2.0f, d2, c2v.x);
            if (e < rv[1][0]) { rv[1][2]=rv[1][1]; ri[1][2]=ri[1][1]; rv[1][1]=rv[1][0]; ri[1][1]=ri[1][0]; rv[1][0]=e; ri[1][0]=code0; }
            else if (e < rv[1][1]) { rv[1][2]=rv[1][1]; ri[1][2]=ri[1][1]; rv[1][1]=e; ri[1][1]=code0; }
            else if (e < rv[1][2]) { rv[1][2]=e; ri[1][2]=code0; }
            e = fmaf(-2.0f, d3, c2v.y);
            if (e < rv[1][0]) { rv[1][2]=rv[1][1]; ri[1][2]=ri[1][1]; rv[1][1]=rv[1][0]; ri[1][1]=ri[1][0]; rv[1][0]=e; ri[1][0]=code1; }
            else if (e < rv[1][1]) { rv[1][2]=rv[1][1]; ri[1][2]=ri[1][1]; rv[1][1]=e; ri[1][1]=code1; }
            else if (e < rv[1][2]) { rv[1][2]=e; ri[1][2]=code1; }
        }
    }

    // Emit candidates: 4 quad-lanes x top-3 = 12 per row.
    #pragma unroll
    for (int h = 0; h < 2; h++) {
        int row  = row0 + rw + g + 8 * h;
        size_t base = (size_t)(row * NUM_CODES + n) * 12 + t * 3;
        #pragma unroll
        for (int j = 0; j < 3; j++) {
            g_cand[base + j] = ri[h][j];
            g_cval[base + j] = rv[h][j];
        }
    }
}

// ---------------------------------------------------------------------------
// Kernel 1.5: resolve each pair from its 12 candidates. (UNCHANGED, passing)
// ---------------------------------------------------------------------------
__global__ void __launch_bounds__(256)
refine_kernel(const float* __restrict__ x, const float* __restrict__ cb) {
    const int warp = threadIdx.x >> 5;
    const int lane = threadIdx.x & 31;
    const int pair = blockIdx.x * 8 + warp;
    if (pair >= NPAIR) return;

    int   cand = 0;
    float val  = 3.4e38f;
    if (lane < 12) {
        cand = g_cand[(size_t)pair * 12 + lane];
        val  = g_cval[(size_t)pair * 12 + lane];
    }

    float vmin = val;
    #pragma unroll
    for (int off = 16; off >= 1; off >>= 1)
        vmin = fminf(vmin, __shfl_xor_sync(0xffffffffu, vmin, off));

    bool active = (lane < 12) && (val <= vmin + MARGIN);
    unsigned actmask = __ballot_sync(0xffffffffu, active);
    int win;

    if (__popc(actmask) == 1) {
        int src = __ffs(actmask) - 1;
        win = __shfl_sync(0xffffffffu, cand, src);
    } else {
        const int b = pair >> 4;
        const int n = pair & 15;
        const float* xr = x + (size_t)b * (NUM_CODES * EMBED_DIM) + n * EMBED_DIM;

        double dj = 1e300;
        for (int j = 0; j < 12; j++) {
            if (!((actmask >> j) & 1u)) continue;
            int cidx = __shfl_sync(0xffffffffu, cand, j);
            const float* cc = cb + ((size_t)n * BOOK_SIZE + cidx) * EMBED_DIM;
            double d = 0.0;
            #pragma unroll
            for (int u = 0; u < 2; u++) {
                int k = lane + 32 * u;
                double xv = (double)xr[k];
                double cv = (double)cc[k];
                d += cv * cv - 2.0 * xv * cv;
            }
            #pragma unroll
            for (int off = 16; off >= 1; off >>= 1)
                d += __shfl_xor_sync(0xffffffffu, d, off);
            if (lane == j) dj = d;
        }

        double dmin = dj;
        #pragma unroll
        for (int off = 16; off >= 1; off >>= 1)
            dmin = fmin(dmin, __shfl_xor_sync(0xffffffffu, dmin, off));

        bool elig = ((actmask >> lane) & 1u) && (lane < 12) && (dj <= dmin + TIE_EPS);
        int key = elig ? cand : 0x7fffffff;
        #pragma unroll
        for (int off = 16; off >= 1; off >>= 1)
            key = min(key, __shfl_xor_sync(0xffffffffu, key, off));
        win = key;
    }

    if (lane == 0) g_idx[pair] = win;
}

// ---------------------------------------------------------------------------
// Kernel 2: write outputs. ONE WARP per (b,n) pair. (UNCHANGED, passing)
// ---------------------------------------------------------------------------
__global__ void __launch_bounds__(256)
write_kernel(const float* __restrict__ cb, float* __restrict__ out) {
    const int warp = threadIdx.x >> 5;
    const int lane = threadIdx.x & 31;
    const int bn   = blockIdx.x * 8 + warp;
    const int b  = bn >> 4;
    const int n  = bn & 15;
    const int idx = g_idx[bn];

    float4* oh = (float4*)(out + CW_ELEMS + (size_t)bn * BOOK_SIZE);
    const int hot4 = idx >> 2;
    #pragma unroll
    for (int i = 0; i < 8; i++) {
        int f4 = i * 32 + lane;
        float4 v = make_float4(0.f, 0.f, 0.f, 0.f);
        if (f4 == hot4) ((float*)&v)[idx & 3] = 1.0f;
        oh[f4] = v;
    }

    if (lane < 16) {
        float4 w = *(const float4*)(cb + ((size_t)n * BOOK_SIZE + idx) * EMBED_DIM + lane * 4);
        *(float4*)(out + (size_t)b * (NUM_CODES * EMBED_DIM) + n * EMBED_DIM + lane * 4) = w;
    }
}

// ---------------------------------------------------------------------------
extern "C" void kernel_launch(void* const* d_in, const int* in_sizes, int n_in,
                              void* d_out, int out_size) {
    const float* x  = (const float*)d_in[0];
    const float* cb = (const float*)d_in[1];
    if (n_in >= 2 && in_sizes[0] == NUM_CODES * BOOK_SIZE * EMBED_DIM) {
        const float* tmp = x; x = cb; cb = tmp;
    }
    float* out = (float*)d_out;

    c2_kernel<<<(NUM_CODES * BOOK_SIZE + 255) / 256, 256>>>(cb);

    dim3 g1(BATCH / MB, NUM_CODES);
    argmin_kernel<<<g1, 256>>>(x, cb);

    refine_kernel<<<NPAIR / 8, 256>>>(x, cb);

    write_kernel<<<NPAIR / 8, 256>>>(cb, out);
}

// round 9
// speedup vs baseline: 2.5203x; 1.3781x over previous
#include <cuda_runtime.h>
#include <cuda_bf16.h>

// Problem constants
#define BATCH     8192
#define NUM_CODES 16
#define BOOK_SIZE 1024
#define EMBED_DIM 64

// Tiling
#define MB     128   // x rows per CTA
#define CHUNK  64    // codebook rows per smem tile

#define NPAIR (BATCH * NUM_CODES)
#define CW_ELEMS ((size_t)BATCH * NUM_CODES * EMBED_DIM)   // 8,388,608

// Near-tie band on EXACT distance gap (proven in R5 pass — do not change)
#define TIE_EPS 4e-5
// refine gate: covers tf32 noise (~0.05 worst) + key truncation (<=0.0625)
#define MARGIN  0.35f
// bias making scores positive so uint order == float order
#define C2BIAS  512.0f

// B-fragment smem: 4 q-blocks of (CHUNK*4 + 1) uint4
#define QBLK (CHUNK * 4 + 1)

// Scratch (device globals; no allocation allowed)
__device__ float g_c2  [NUM_CODES * BOOK_SIZE];   // stores c2 + C2BIAS
__device__ int   g_cand[(size_t)NPAIR * 12];
__device__ float g_cval[(size_t)NPAIR * 12];
__device__ int   g_idx [NPAIR];

// ---------------------------------------------------------------------------
__device__ __forceinline__ unsigned int f2tf32(float f) {
    unsigned int r;
    asm("cvt.rna.tf32.f32 %0, %1;" : "=r"(r) : "f"(f));
    return r;
}
__device__ __forceinline__ void mma_tf32(float& d0, float& d1, float& d2, float& d3,
                                         unsigned int a0, unsigned int a1,
                                         unsigned int a2, unsigned int a3,
                                         unsigned int b0, unsigned int b1) {
    asm("mma.sync.aligned.m16n8k8.row.col.f32.tf32.tf32.f32 "
        "{%0,%1,%2,%3}, {%4,%5,%6,%7}, {%8,%9}, {%0,%1,%2,%3};"
        : "+f"(d0), "+f"(d1), "+f"(d2), "+f"(d3)
        : "r"(a0), "r"(a1), "r"(a2), "r"(a3), "r"(b0), "r"(b1));
}

// top-3 (ascending) insertion of key k into sorted triple: 5 integer min/max
__device__ __forceinline__ void ins3(unsigned int& k0, unsigned int& k1,
                                     unsigned int& k2, unsigned int k) {
    unsigned int a = umin(k, k0);
    unsigned int b = umax(k, k0);
    unsigned int c = umin(b, k1);
    unsigned int d = umax(b, k1);
    k2 = umin(d, k2);
    k1 = c;
    k0 = a;
}

// ---------------------------------------------------------------------------
// Kernel 0: codebook squared norms + bias (ranking only; refine re-derives
// exact values for borderline pairs).
// ---------------------------------------------------------------------------
__global__ void c2_kernel(const float* __restrict__ cb) {
    int code = blockIdx.x * blockDim.x + threadIdx.x;
    if (code < NUM_CODES * BOOK_SIZE) {
        const float4* p = (const float4*)(cb + (size_t)code * EMBED_DIM);
        float s = 0.f;
        #pragma unroll
        for (int i = 0; i < EMBED_DIM / 4; i++) {
            float4 v = p[i];
            s += v.x * v.x + v.y * v.y + v.z * v.z + v.w * v.w;
        }
        g_c2[code] = s + C2BIAS;
    }
}

// ---------------------------------------------------------------------------
// Kernel 1: tf32 tensor-core distance ranking, per-thread top-3 candidates
// kept as packed keys: key = (bits of (c2 + 512 - 2*dot) & ~0x3FF) | code.
// Positive floats -> uint order == float order; code in low 10 bits makes
// exact ties resolve to the lowest index. Grid (BATCH/MB, NUM_CODES).
// ---------------------------------------------------------------------------
__global__ void __launch_bounds__(256)
argmin_kernel(const float* __restrict__ x, const float* __restrict__ cb) {
    __shared__ float xs[EMBED_DIM][MB];        // 32 KB, transposed x tile
    __shared__ uint4 csf[4 * QBLK];            // ~16.4 KB, tf32 B fragments

    const int tid  = threadIdx.x;
    const int w    = tid >> 5;
    const int lane = tid & 31;
    const int g    = lane >> 2;
    const int t    = lane & 3;
    const int n    = blockIdx.y;
    const int row0 = blockIdx.x * MB;
    const int rw   = w * 16;   // warp's row base within tile

    const float* xbase = x  + (size_t)row0 * (NUM_CODES * EMBED_DIM) + n * EMBED_DIM;
    const float* cbase = cb + (size_t)n * (BOOK_SIZE * EMBED_DIM);
    const float* c2b   = &g_c2[n * BOOK_SIZE];

    // Load x tile (transposed). 128 rows x 16 float4 columns, coalesced.
    for (int it = tid; it < MB * (EMBED_DIM / 4); it += 256) {
        int r  = it >> 4;
        int c4 = it & 15;
        float4 v = *(const float4*)(xbase + (size_t)r * (NUM_CODES * EMBED_DIM) + c4 * 4);
        xs[c4 * 4 + 0][r] = v.x;
        xs[c4 * 4 + 1][r] = v.y;
        xs[c4 * 4 + 2][r] = v.z;
        xs[c4 * 4 + 3][r] = v.w;
    }
    __syncthreads();

    // A fragments for the full K=64 (8 k-steps), loaded once, kept as tf32.
    unsigned int a[8][4];
    #pragma unroll
    for (int s = 0; s < 8; s++) {
        a[s][0] = f2tf32(xs[8 * s + t    ][rw + g    ]);
        a[s][1] = f2tf32(xs[8 * s + t    ][rw + g + 8]);
        a[s][2] = f2tf32(xs[8 * s + t + 4][rw + g    ]);
        a[s][3] = f2tf32(xs[8 * s + t + 4][rw + g + 8]);
    }

    // Per-thread top-3 packed keys for each of the 2 rows this thread owns.
    unsigned int kk[2][3];
    #pragma unroll
    for (int h = 0; h < 2; h++)
        #pragma unroll
        for (int j = 0; j < 3; j++) kk[h][j] = 0xFFFFFFFFu;

    unsigned int* csf32 = (unsigned int*)csf;

    for (int c0 = 0; c0 < BOOK_SIZE; c0 += CHUNK) {
        __syncthreads();
        // Fill csf: CHUNK codes x 16 float4 columns; convert to tf32 once.
        for (int it = tid; it < CHUNK * (EMBED_DIM / 4); it += 256) {
            int code = it >> 4;
            int c4   = it & 15;
            int q    = c4 >> 2;
            int inr  = c4 & 3;
            float4 v = *(const float4*)(cbase + (size_t)(c0 + code) * EMBED_DIM + c4 * 4);
            unsigned int base = (q * QBLK + code * 4) * 4 + inr;
            csf32[base     ] = f2tf32(v.x);
            csf32[base + 4 ] = f2tf32(v.y);
            csf32[base + 8 ] = f2tf32(v.z);
            csf32[base + 12] = f2tf32(v.w);
        }
        __syncthreads();

        #pragma unroll
        for (int tc = 0; tc < CHUNK / 8; tc++) {
            const int cbs = tc * 8;
            const int cg  = c0 + cbs;
            const int code = cbs + g;

            uint4 Q0 = csf[0 * QBLK + code * 4 + t];
            uint4 Q1 = csf[1 * QBLK + code * 4 + t];
            uint4 Q2 = csf[2 * QBLK + code * 4 + t];
            uint4 Q3 = csf[3 * QBLK + code * 4 + t];

            float d0 = 0.f, d1 = 0.f, d2 = 0.f, d3 = 0.f;
            mma_tf32(d0, d1, d2, d3, a[0][0], a[0][1], a[0][2], a[0][3], Q0.x, Q0.y);
            mma_tf32(d0, d1, d2, d3, a[1][0], a[1][1], a[1][2], a[1][3], Q0.z, Q0.w);
            mma_tf32(d0, d1, d2, d3, a[2][0], a[2][1], a[2][2], a[2][3], Q1.x, Q1.y);
            mma_tf32(d0, d1, d2, d3, a[3][0], a[3][1], a[3][2], a[3][3], Q1.z, Q1.w);
            mma_tf32(d0, d1, d2, d3, a[4][0], a[4][1], a[4][2], a[4][3], Q2.x, Q2.y);
            mma_tf32(d0, d1, d2, d3, a[5][0], a[5][1], a[5][2], a[5][3], Q2.z, Q2.w);
            mma_tf32(d0, d1, d2, d3, a[6][0], a[6][1], a[6][2], a[6][3], Q3.x, Q3.y);
            mma_tf32(d0, d1, d2, d3, a[7][0], a[7][1], a[7][2], a[7][3], Q3.z, Q3.w);

            // packed-key epilogue: 4 x (FFMA + LOP3 + 5 IMNMX)
            float2 c2v = *(const float2*)(c2b + cg + 2 * t);   // biased c2
            unsigned int code0 = cg + 2 * t, code1 = code0 + 1;

            unsigned int k;
            k = (__float_as_uint(fmaf(-2.0f, d0, c2v.x)) & 0xFFFFFC00u) | code0;
            ins3(kk[0][0], kk[0][1], kk[0][2], k);
            k = (__float_as_uint(fmaf(-2.0f, d1, c2v.y)) & 0xFFFFFC00u) | code1;
            ins3(kk[0][0], kk[0][1], kk[0][2], k);
            k = (__float_as_uint(fmaf(-2.0f, d2, c2v.x)) & 0xFFFFFC00u) | code0;
            ins3(kk[1][0], kk[1][1], kk[1][2], k);
            k = (__float_as_uint(fmaf(-2.0f, d3, c2v.y)) & 0xFFFFFC00u) | code1;
            ins3(kk[1][0], kk[1][1], kk[1][2], k);
        }
    }

    // Emit candidates: 4 quad-lanes x top-3 = 12 per row.
    #pragma unroll
    for (int h = 0; h < 2; h++) {
        int row  = row0 + rw + g + 8 * h;
        size_t base = (size_t)(row * NUM_CODES + n) * 12 + t * 3;
        #pragma unroll
        for (int j = 0; j < 3; j++) {
            g_cand[base + j] = (int)(kk[h][j] & 0x3FFu);
            g_cval[base + j] = __uint_as_float(kk[h][j] & 0xFFFFFC00u) - C2BIAS;
        }
    }
}

// ---------------------------------------------------------------------------
// Kernel 1.5: resolve each pair from its 12 candidates. (logic unchanged)
// ---------------------------------------------------------------------------
__global__ void __launch_bounds__(256)
refine_kernel(const float* __restrict__ x, const float* __restrict__ cb) {
    const int warp = threadIdx.x >> 5;
    const int lane = threadIdx.x & 31;
    const int pair = blockIdx.x * 8 + warp;
    if (pair >= NPAIR) return;

    int   cand = 0;
    float val  = 3.4e38f;
    if (lane < 12) {
        cand = g_cand[(size_t)pair * 12 + lane];
        val  = g_cval[(size_t)pair * 12 + lane];
    }

    float vmin = val;
    #pragma unroll
    for (int off = 16; off >= 1; off >>= 1)
        vmin = fminf(vmin, __shfl_xor_sync(0xffffffffu, vmin, off));

    bool active = (lane < 12) && (val <= vmin + MARGIN);
    unsigned actmask = __ballot_sync(0xffffffffu, active);
    int win;

    if (__popc(actmask) == 1) {
        int src = __ffs(actmask) - 1;
        win = __shfl_sync(0xffffffffu, cand, src);
    } else {
        const int b = pair >> 4;
        const int n = pair & 15;
        const float* xr = x + (size_t)b * (NUM_CODES * EMBED_DIM) + n * EMBED_DIM;

        double dj = 1e300;
        for (int j = 0; j < 12; j++) {
            if (!((actmask >> j) & 1u)) continue;
            int cidx = __shfl_sync(0xffffffffu, cand, j);
            const float* cc = cb + ((size_t)n * BOOK_SIZE + cidx) * EMBED_DIM;
            double d = 0.0;
            #pragma unroll
            for (int u = 0; u < 2; u++) {
                int k = lane + 32 * u;
                double xv = (double)xr[k];
                double cv = (double)cc[k];
                d += cv * cv - 2.0 * xv * cv;
            }
            #pragma unroll
            for (int off = 16; off >= 1; off >>= 1)
                d += __shfl_xor_sync(0xffffffffu, d, off);
            if (lane == j) dj = d;
        }

        double dmin = dj;
        #pragma unroll
        for (int off = 16; off >= 1; off >>= 1)
            dmin = fmin(dmin, __shfl_xor_sync(0xffffffffu, dmin, off));

        bool elig = ((actmask >> lane) & 1u) && (lane < 12) && (dj <= dmin + TIE_EPS);
        int key = elig ? cand : 0x7fffffff;
        #pragma unroll
        for (int off = 16; off >= 1; off >>= 1)
            key = min(key, __shfl_xor_sync(0xffffffffu, key, off));
        win = key;
    }

    if (lane == 0) g_idx[pair] = win;
}

// ---------------------------------------------------------------------------
// Kernel 2: write outputs. ONE WARP per (b,n) pair; streaming stores.
// ---------------------------------------------------------------------------
__global__ void __launch_bounds__(256)
write_kernel(const float* __restrict__ cb, float* __restrict__ out) {
    const int warp = threadIdx.x >> 5;
    const int lane = threadIdx.x & 31;
    const int bn   = blockIdx.x * 8 + warp;
    const int b  = bn >> 4;
    const int n  = bn & 15;
    const int idx = g_idx[bn];

    float4* oh = (float4*)(out + CW_ELEMS + (size_t)bn * BOOK_SIZE);
    const int hot4 = idx >> 2;
    #pragma unroll
    for (int i = 0; i < 8; i++) {
        int f4 = i * 32 + lane;
        float4 v = make_float4(0.f, 0.f, 0.f, 0.f);
        if (f4 == hot4) ((float*)&v)[idx & 3] = 1.0f;
        __stwt(&oh[f4], v);
    }

    if (lane < 16) {
        float4 w = *(const float4*)(cb + ((size_t)n * BOOK_SIZE + idx) * EMBED_DIM + lane * 4);
        __stwt((float4*)(out + (size_t)b * (NUM_CODES * EMBED_DIM) + n * EMBED_DIM + lane * 4), w);
    }
}

// ---------------------------------------------------------------------------
extern "C" void kernel_launch(void* const* d_in, const int* in_sizes, int n_in,
                              void* d_out, int out_size) {
    const float* x  = (const float*)d_in[0];
    const float* cb = (const float*)d_in[1];
    if (n_in >= 2 && in_sizes[0] == NUM_CODES * BOOK_SIZE * EMBED_DIM) {
        const float* tmp = x; x = cb; cb = tmp;
    }
    float* out = (float*)d_out;

    c2_kernel<<<(NUM_CODES * BOOK_SIZE + 255) / 256, 256>>>(cb);

    dim3 g1(BATCH / MB, NUM_CODES);
    argmin_kernel<<<g1, 256>>>(x, cb);

    refine_kernel<<<NPAIR / 8, 256>>>(x, cb);

    write_kernel<<<NPAIR / 8, 256>>>(cb, out);
}

// round 10
// speedup vs baseline: 2.9650x; 1.1764x over previous
#include <cuda_runtime.h>
#include <cuda_bf16.h>

// Problem constants
#define BATCH     8192
#define NUM_CODES 16
#define BOOK_SIZE 1024
#define EMBED_DIM 64

// Tiling
#define MB     128   // x rows per CTA
#define CHUNK  64    // codebook rows per smem tile

#define NPAIR (BATCH * NUM_CODES)
#define CW_ELEMS ((size_t)BATCH * NUM_CODES * EMBED_DIM)   // 8,388,608

// Near-tie band on EXACT distance gap (proven in R5 pass — do not change)
#define TIE_EPS 4e-5
// refine gate: covers tf32 noise (~0.05 worst) + key truncation (<=0.0625)
#define MARGIN  0.35f
// bias making scores positive so uint order == float order
#define C2BIAS  512.0f

// B-fragment smem: 4 q-blocks of (CHUNK*4 + 1) uint4
#define QBLK (CHUNK * 4 + 1)

// Scratch (device globals; no allocation allowed)
__device__ float g_c2  [NUM_CODES * BOOK_SIZE];   // stores c2 + C2BIAS
__device__ int   g_cand[(size_t)NPAIR * 12];
__device__ float g_cval[(size_t)NPAIR * 12];
__device__ int   g_idx [NPAIR];

// ---------------------------------------------------------------------------
__device__ __forceinline__ unsigned int f2tf32(float f) {
    unsigned int r;
    asm("cvt.rna.tf32.f32 %0, %1;" : "=r"(r) : "f"(f));
    return r;
}
__device__ __forceinline__ void mma_tf32(float& d0, float& d1, float& d2, float& d3,
                                         unsigned int a0, unsigned int a1,
                                         unsigned int a2, unsigned int a3,
                                         unsigned int b0, unsigned int b1) {
    asm("mma.sync.aligned.m16n8k8.row.col.f32.tf32.tf32.f32 "
        "{%0,%1,%2,%3}, {%4,%5,%6,%7}, {%8,%9}, {%0,%1,%2,%3};"
        : "+f"(d0), "+f"(d1), "+f"(d2), "+f"(d3)
        : "r"(a0), "r"(a1), "r"(a2), "r"(a3), "r"(b0), "r"(b1));
}

// top-3 (ascending) insertion of key k into sorted triple: 5 integer min/max
__device__ __forceinline__ void ins3(unsigned int& k0, unsigned int& k1,
                                     unsigned int& k2, unsigned int k) {
    unsigned int a = umin(k, k0);
    unsigned int b = umax(k, k0);
    unsigned int c = umin(b, k1);
    unsigned int d = umax(b, k1);
    k2 = umin(d, k2);
    k1 = c;
    k0 = a;
}

// ---------------------------------------------------------------------------
// Kernel 0: codebook squared norms + bias.
// ---------------------------------------------------------------------------
__global__ void c2_kernel(const float* __restrict__ cb) {
    int code = blockIdx.x * blockDim.x + threadIdx.x;
    if (code < NUM_CODES * BOOK_SIZE) {
        const float4* p = (const float4*)(cb + (size_t)code * EMBED_DIM);
        float s = 0.f;
        #pragma unroll
        for (int i = 0; i < EMBED_DIM / 4; i++) {
            float4 v = p[i];
            s += v.x * v.x + v.y * v.y + v.z * v.z + v.w * v.w;
        }
        g_c2[code] = s + C2BIAS;
    }
}

// ---------------------------------------------------------------------------
// Kernel 1: tf32 tensor-core ranking + fused one-hot zero-fill.
// 128 threads = 4 warps; warp w owns rows [w*32, w*32+32) as TWO m16 A-sets,
// halving redundant B-fragment smem reads vs 8 thin warps.
// While computing, each CTA streams zeros into the one-hot rows of its own
// (row, n) pairs (512 KB) with __stwt — DRAM writes drain under compute.
// Keys: (bits of (c2 + 512 - 2*dot) & ~0x3FF) | code  (uint order = float
// order for positives; low-bits code -> ties resolve to lowest index).
// ---------------------------------------------------------------------------
__global__ void __launch_bounds__(128)
argmin_kernel(const float* __restrict__ x, const float* __restrict__ cb,
              float* __restrict__ out) {
    __shared__ float xs[EMBED_DIM][MB];        // 32 KB, transposed x tile
    __shared__ uint4 csf[4 * QBLK];            // ~16.4 KB, tf32 B fragments

    const int tid  = threadIdx.x;
    const int w    = tid >> 5;
    const int lane = tid & 31;
    const int g    = lane >> 2;
    const int t    = lane & 3;
    const int n    = blockIdx.y;
    const int row0 = blockIdx.x * MB;
    const int rw   = w * 32;   // warp's row base within tile (32 rows)

    const float* xbase = x  + (size_t)row0 * (NUM_CODES * EMBED_DIM) + n * EMBED_DIM;
    const float* cbase = cb + (size_t)n * (BOOK_SIZE * EMBED_DIM);
    const float* c2b   = &g_c2[n * BOOK_SIZE];
    // one-hot zero-fill base for this CTA's pairs: rows (row0+r)*16+n
    float4* ohz = (float4*)(out + CW_ELEMS + ((size_t)row0 * NUM_CODES + n) * BOOK_SIZE);
    const float4 zero4 = make_float4(0.f, 0.f, 0.f, 0.f);

    // Load x tile (transposed). 128 rows x 16 float4 columns, coalesced.
    for (int it = tid; it < MB * (EMBED_DIM / 4); it += 128) {
        int r  = it >> 4;
        int c4 = it & 15;
        float4 v = *(const float4*)(xbase + (size_t)r * (NUM_CODES * EMBED_DIM) + c4 * 4);
        xs[c4 * 4 + 0][r] = v.x;
        xs[c4 * 4 + 1][r] = v.y;
        xs[c4 * 4 + 2][r] = v.z;
        xs[c4 * 4 + 3][r] = v.w;
    }
    __syncthreads();

    // A fragments, two m16 row-sets, full K=64 (8 k-steps), kept as tf32.
    unsigned int a[2][8][4];
    #pragma unroll
    for (int m = 0; m < 2; m++) {
        const int rb = rw + m * 16;
        #pragma unroll
        for (int s = 0; s < 8; s++) {
            a[m][s][0] = f2tf32(xs[8 * s + t    ][rb + g    ]);
            a[m][s][1] = f2tf32(xs[8 * s + t    ][rb + g + 8]);
            a[m][s][2] = f2tf32(xs[8 * s + t + 4][rb + g    ]);
            a[m][s][3] = f2tf32(xs[8 * s + t + 4][rb + g + 8]);
        }
    }

    // Per-thread top-3 packed keys for each of the 4 rows this thread owns.
    unsigned int kk[4][3];
    #pragma unroll
    for (int h = 0; h < 4; h++)
        #pragma unroll
        for (int j = 0; j < 3; j++) kk[h][j] = 0xFFFFFFFFu;

    unsigned int* csf32 = (unsigned int*)csf;
    int it2 = 0;   // zero-fill progress counter (2 float4 per tile iter)

    for (int c0 = 0; c0 < BOOK_SIZE; c0 += CHUNK) {
        __syncthreads();
        // Fill csf: CHUNK codes x 16 float4 columns; convert to tf32 once.
        for (int it = tid; it < CHUNK * (EMBED_DIM / 4); it += 128) {
            int code = it >> 4;
            int c4   = it & 15;
            int q    = c4 >> 2;
            int inr  = c4 & 3;
            float4 v = *(const float4*)(cbase + (size_t)(c0 + code) * EMBED_DIM + c4 * 4);
            unsigned int base = (q * QBLK + code * 4) * 4 + inr;
            csf32[base     ] = f2tf32(v.x);
            csf32[base + 4 ] = f2tf32(v.y);
            csf32[base + 8 ] = f2tf32(v.z);
            csf32[base + 12] = f2tf32(v.w);
        }
        __syncthreads();

        #pragma unroll
        for (int tc = 0; tc < CHUNK / 8; tc++) {
            const int cbs = tc * 8;
            const int cg  = c0 + cbs;
            const int code = cbs + g;

            // background one-hot zero-fill: 2 coalesced float4 per thread
            {
                int j0 = it2 * 2;
                int L0 = j0 * 128 + tid;          // row = L>>8, f4 = L&255
                int L1 = L0 + 128;
                __stwt(&ohz[((size_t)(L0 >> 8)) * (NUM_CODES * 256) + (L0 & 255)], zero4);
                __stwt(&ohz[((size_t)(L1 >> 8)) * (NUM_CODES * 256) + (L1 & 255)], zero4);
                it2++;
            }

            uint4 Q0 = csf[0 * QBLK + code * 4 + t];
            uint4 Q1 = csf[1 * QBLK + code * 4 + t];
            uint4 Q2 = csf[2 * QBLK + code * 4 + t];
            uint4 Q3 = csf[3 * QBLK + code * 4 + t];

            float2 c2v = *(const float2*)(c2b + cg + 2 * t);   // biased c2
            unsigned int code0 = cg + 2 * t, code1 = code0 + 1;

            #pragma unroll
            for (int m = 0; m < 2; m++) {
                float d0 = 0.f, d1 = 0.f, d2 = 0.f, d3 = 0.f;
                mma_tf32(d0, d1, d2, d3, a[m][0][0], a[m][0][1], a[m][0][2], a[m][0][3], Q0.x, Q0.y);
                mma_tf32(d0, d1, d2, d3, a[m][1][0], a[m][1][1], a[m][1][2], a[m][1][3], Q0.z, Q0.w);
                mma_tf32(d0, d1, d2, d3, a[m][2][0], a[m][2][1], a[m][2][2], a[m][2][3], Q1.x, Q1.y);
                mma_tf32(d0, d1, d2, d3, a[m][3][0], a[m][3][1], a[m][3][2], a[m][3][3], Q1.z, Q1.w);
                mma_tf32(d0, d1, d2, d3, a[m][4][0], a[m][4][1], a[m][4][2], a[m][4][3], Q2.x, Q2.y);
                mma_tf32(d0, d1, d2, d3, a[m][5][0], a[m][5][1], a[m][5][2], a[m][5][3], Q2.z, Q2.w);
                mma_tf32(d0, d1, d2, d3, a[m][6][0], a[m][6][1], a[m][6][2], a[m][6][3], Q3.x, Q3.y);
                mma_tf32(d0, d1, d2, d3, a[m][7][0], a[m][7][1], a[m][7][2], a[m][7][3], Q3.z, Q3.w);

                unsigned int k;
                k = (__float_as_uint(fmaf(-2.0f, d0, c2v.x)) & 0xFFFFFC00u) | code0;
                ins3(kk[2*m][0], kk[2*m][1], kk[2*m][2], k);
                k = (__float_as_uint(fmaf(-2.0f, d1, c2v.y)) & 0xFFFFFC00u) | code1;
                ins3(kk[2*m][0], kk[2*m][1], kk[2*m][2], k);
                k = (__float_as_uint(fmaf(-2.0f, d2, c2v.x)) & 0xFFFFFC00u) | code0;
                ins3(kk[2*m+1][0], kk[2*m+1][1], kk[2*m+1][2], k);
                k = (__float_as_uint(fmaf(-2.0f, d3, c2v.y)) & 0xFFFFFC00u) | code1;
                ins3(kk[2*m+1][0], kk[2*m+1][1], kk[2*m+1][2], k);
            }
        }
    }

    // Emit candidates: 4 quad-lanes x top-3 = 12 per row.
    // h = 2m + hh -> row = row0 + rw + m*16 + g + hh*8
    #pragma unroll
    for (int h = 0; h < 4; h++) {
        int row  = row0 + rw + (h >> 1) * 16 + g + (h & 1) * 8;
        size_t base = (size_t)(row * NUM_CODES + n) * 12 + t * 3;
        #pragma unroll
        for (int j = 0; j < 3; j++) {
            g_cand[base + j] = (int)(kk[h][j] & 0x3FFu);
            g_cval[base + j] = __uint_as_float(kk[h][j] & 0xFFFFFC00u) - C2BIAS;
        }
    }
}

// ---------------------------------------------------------------------------
// Kernel 1.5: resolve each pair from its 12 candidates. (logic unchanged)
// ---------------------------------------------------------------------------
__global__ void __launch_bounds__(256)
refine_kernel(const float* __restrict__ x, const float* __restrict__ cb) {
    const int warp = threadIdx.x >> 5;
    const int lane = threadIdx.x & 31;
    const int pair = blockIdx.x * 8 + warp;
    if (pair >= NPAIR) return;

    int   cand = 0;
    float val  = 3.4e38f;
    if (lane < 12) {
        cand = g_cand[(size_t)pair * 12 + lane];
        val  = g_cval[(size_t)pair * 12 + lane];
    }

    float vmin = val;
    #pragma unroll
    for (int off = 16; off >= 1; off >>= 1)
        vmin = fminf(vmin, __shfl_xor_sync(0xffffffffu, vmin, off));

    bool active = (lane < 12) && (val <= vmin + MARGIN);
    unsigned actmask = __ballot_sync(0xffffffffu, active);
    int win;

    if (__popc(actmask) == 1) {
        int src = __ffs(actmask) - 1;
        win = __shfl_sync(0xffffffffu, cand, src);
    } else {
        const int b = pair >> 4;
        const int n = pair & 15;
        const float* xr = x + (size_t)b * (NUM_CODES * EMBED_DIM) + n * EMBED_DIM;

        double dj = 1e300;
        for (int j = 0; j < 12; j++) {
            if (!((actmask >> j) & 1u)) continue;
            int cidx = __shfl_sync(0xffffffffu, cand, j);
            const float* cc = cb + ((size_t)n * BOOK_SIZE + cidx) * EMBED_DIM;
            double d = 0.0;
            #pragma unroll
            for (int u = 0; u < 2; u++) {
                int k = lane + 32 * u;
                double xv = (double)xr[k];
                double cv = (double)cc[k];
                d += cv * cv - 2.0 * xv * cv;
            }
            #pragma unroll
            for (int off = 16; off >= 1; off >>= 1)
                d += __shfl_xor_sync(0xffffffffu, d, off);
            if (lane == j) dj = d;
        }

        double dmin = dj;
        #pragma unroll
        for (int off = 16; off >= 1; off >>= 1)
            dmin = fmin(dmin, __shfl_xor_sync(0xffffffffu, dmin, off));

        bool elig = ((actmask >> lane) & 1u) && (lane < 12) && (dj <= dmin + TIE_EPS);
        int key = elig ? cand : 0x7fffffff;
        #pragma unroll
        for (int off = 16; off >= 1; off >>= 1)
            key = min(key, __shfl_xor_sync(0xffffffffu, key, off));
        win = key;
    }

    if (lane == 0) g_idx[pair] = win;
}

// ---------------------------------------------------------------------------
// Kernel 2: finalize outputs. One warp per (b,n) pair.
// One-hot zeros already streamed by argmin_kernel; here only the 1.0f hot
// element (scattered 4B store) + the 64-float codeword gather.
// ---------------------------------------------------------------------------
__global__ void __launch_bounds__(256)
write_kernel(const float* __restrict__ cb, float* __restrict__ out) {
    const int warp = threadIdx.x >> 5;
    const int lane = threadIdx.x & 31;
    const int bn   = blockIdx.x * 8 + warp;
    const int b  = bn >> 4;
    const int n  = bn & 15;
    const int idx = g_idx[bn];

    if (lane == 0)
        out[CW_ELEMS + (size_t)bn * BOOK_SIZE + idx] = 1.0f;

    if (lane < 16) {
        float4 w = *(const float4*)(cb + ((size_t)n * BOOK_SIZE + idx) * EMBED_DIM + lane * 4);
        __stwt((float4*)(out + (size_t)b * (NUM_CODES * EMBED_DIM) + n * EMBED_DIM + lane * 4), w);
    }
}

// ---------------------------------------------------------------------------
extern "C" void kernel_launch(void* const* d_in, const int* in_sizes, int n_in,
                              void* d_out, int out_size) {
    const float* x  = (const float*)d_in[0];
    const float* cb = (const float*)d_in[1];
    if (n_in >= 2 && in_sizes[0] == NUM_CODES * BOOK_SIZE * EMBED_DIM) {
        const float* tmp = x; x = cb; cb = tmp;
    }
    float* out = (float*)d_out;

    c2_kernel<<<(NUM_CODES * BOOK_SIZE + 255) / 256, 256>>>(cb);

    dim3 g1(BATCH / MB, NUM_CODES);
    argmin_kernel<<<g1, 128>>>(x, cb, out);

    refine_kernel<<<NPAIR / 8, 256>>>(x, cb);

    write_kernel<<<NPAIR / 8, 256>>>(cb, out);
}